// round 9
// baseline (speedup 1.0000x reference)
#include <cuda_runtime.h>

#define T_ 1024
#define B_ 128
#define L_ 128
#define STRIDE_ (B_ * L_)

typedef unsigned long long ull;

// scratch (no allocations allowed)
__device__ float g_den[B_];
__device__ float g_num[B_];

__device__ __forceinline__ ull ffma2(ull a, ull b, ull c) {
    ull d;
    asm("fma.rn.f32x2 %0, %1, %2, %3;" : "=l"(d) : "l"(a), "l"(b), "l"(c));
    return d;
}
__device__ __forceinline__ ull add2(ull a, ull b) {
    ull d;
    asm("add.rn.f32x2 %0, %1, %2;" : "=l"(d) : "l"(a), "l"(b));
    return d;
}
__device__ __forceinline__ ull pack2(float lo, float hi) {
    ull d;
    asm("mov.b64 %0, {%1, %2};" : "=l"(d) : "f"(lo), "f"(hi));
    return d;
}
__device__ __forceinline__ float2 unpack2(ull v) {
    float2 f;
    asm("mov.b64 {%0, %1}, %2;" : "=f"(f.x), "=f"(f.y) : "l"(v));
    return f;
}

#define BSYNC(id) asm volatile("bar.sync %0, 128;"   :: "r"(id) : "memory")
#define BARR(id)  asm volatile("bar.arrive %0, 128;" :: "r"(id) : "memory")

// ---------------------------------------------------------------------------
// Denominator. One block (128 thr) per batch b; thread j owns state/column j.
// Warp-ring pipeline, GLOBAL-ORDER sync (deadlock-free): every warp consumes
// u_{t-1} chunks in ascending order c = 0,1,2,3; before reading a FOREIGN
// chunk it does bar.sync on that chunk's named barrier; its OWN chunk needs
// no sync. After producing its 32 outputs it does bar.arrive on its own
// chunk's barrier. Barrier id = 1 + 2c + parity(t); each use collects
// 32 (producer arrive) + 96 (3 consumer syncs) = 128 arrivals.
// Acyclic: barrier c only waits on warps whose earlier syncs are on
// barriers < c. WAR-safe: producer w's overwrite of chunk w at step t+2 is
// ordered after all step-t+1 reads via w's syncs on the readers' arrives.
// No full-block barrier in the main loop -> warps skew instead of lockstep.
// Renormalize by broadcast u[0] every 4 steps (exact for any positive scale).
// ---------------------------------------------------------------------------
__global__ __launch_bounds__(L_) void crf_den_kernel(
    const float* __restrict__ pred,    // (T,B,L)
    const int*   __restrict__ mask,    // (T,B)
    const float* __restrict__ trans,   // (L,L)
    const float* __restrict__ start,   // (L)
    const float* __restrict__ endv)    // (L)
{
    const int b    = blockIdx.x;
    const int j    = threadIdx.x;
    const int lane = j & 31;
    const int w    = j >> 5;

    // exp(transitions) column j, packed row pairs, natural chunk order:
    // rT2[c*16 + k] covers source rows i = 32c + 2k, 32c + 2k + 1.
    ull rT2[64];
#pragma unroll
    for (int k = 0; k < 64; ++k)
        rT2[k] = pack2(expf(trans[(2 * k) * L_ + j]),
                       expf(trans[(2 * k + 1) * L_ + j]));

    __shared__ __align__(16) float e_sh[2][L_];
    __shared__ int   m_sh[T_ + 4];
    __shared__ float red[4];

    // preload mask column b (one time), pad the tail
#pragma unroll
    for (int t = j; t < T_; t += L_)
        m_sh[t] = mask[t * B_ + b];
    if (j < 4) m_sh[T_ + j] = 0;

    const float* pj = pred + b * L_ + j;

    float u    = __expf(start[j] + pj[0]);   // t = 0
    float logZ = 0.0f;
    e_sh[0][j] = u;
    __syncthreads();                 // e_sh[0] + m_sh visible to all
    BARR(1 + (w << 1));              // arrive own chunk, parity 0

    // depth-4 prediction prefetch ring; slot (t-1)&3 holds p_t
    float pr0 = pj[(size_t)1 << 14];
    float pr1 = pj[(size_t)2 << 14];
    float pr2 = pj[(size_t)3 << 14];
    float pr3 = pj[(size_t)4 << 14];

    float ep_cur = __expf(pr0);      // exp(p_1)
    int   mk_cur = m_sh[1];

#define PLOAD(tl) (((tl) < T_) ? pj[(size_t)(tl) << 14] : 0.0f)

// PC_: parity of consumed buffer ((t-1)&1); PW_: parity written (t&1).
#define STEP(t_, PRcur_, PRnxt_, RN_, PC_, PW_)                               \
    do {                                                                      \
        ull a0 = 0ull, a1 = 0ull, a2 = 0ull, a3 = 0ull;                       \
        ull a4 = 0ull, a5 = 0ull, a6 = 0ull, a7 = 0ull;                       \
        _Pragma("unroll")                                                     \
        for (int c = 0; c < 4; ++c) {                                         \
            if (c != w) BSYNC(1 + (c << 1) + (PC_));                          \
            const ulonglong2* ev =                                            \
                reinterpret_cast<const ulonglong2*>(&e_sh[PC_][c << 5]);      \
            ulonglong2 v0 = ev[0], v1 = ev[1], v2 = ev[2], v3 = ev[3];        \
            a0 = ffma2(v0.x, rT2[c * 16 + 0], a0);                            \
            a1 = ffma2(v0.y, rT2[c * 16 + 1], a1);                            \
            a2 = ffma2(v1.x, rT2[c * 16 + 2], a2);                            \
            a3 = ffma2(v1.y, rT2[c * 16 + 3], a3);                            \
            a4 = ffma2(v2.x, rT2[c * 16 + 4], a4);                            \
            a5 = ffma2(v2.y, rT2[c * 16 + 5], a5);                            \
            a6 = ffma2(v3.x, rT2[c * 16 + 6], a6);                            \
            a7 = ffma2(v3.y, rT2[c * 16 + 7], a7);                            \
            ulonglong2 v4 = ev[4], v5 = ev[5], v6 = ev[6], v7 = ev[7];        \
            a0 = ffma2(v4.x, rT2[c * 16 + 8],  a0);                           \
            a1 = ffma2(v4.y, rT2[c * 16 + 9],  a1);                           \
            a2 = ffma2(v5.x, rT2[c * 16 + 10], a2);                           \
            a3 = ffma2(v5.y, rT2[c * 16 + 11], a3);                           \
            a4 = ffma2(v6.x, rT2[c * 16 + 12], a4);                           \
            a5 = ffma2(v6.y, rT2[c * 16 + 13], a5);                           \
            a6 = ffma2(v7.x, rT2[c * 16 + 14], a6);                           \
            a7 = ffma2(v7.y, rT2[c * 16 + 15], a7);                           \
        }                                                                     \
        a0 = add2(a0, a1); a2 = add2(a2, a3);                                 \
        a4 = add2(a4, a5); a6 = add2(a6, a7);                                 \
        a0 = add2(a0, a2); a4 = add2(a4, a6);                                 \
        a0 = add2(a0, a4);                                                    \
        float2 fx = unpack2(a0);                                              \
        const float part = fx.x + fx.y;                                       \
        float inv_m = 1.0f;                                                   \
        if (RN_) {                                                            \
            const float mval = e_sh[PC_][0];                                  \
            logZ += __logf(mval);                                             \
            inv_m = 1.0f / mval;                                              \
        }                                                                     \
        u = (mk_cur ? part * ep_cur : u) * inv_m;                             \
        e_sh[PW_][j] = u;                                                     \
        __syncwarp();                                                         \
        BARR(1 + (w << 1) + (PW_));                                           \
        PRcur_ = PLOAD((t_) + 4);                                             \
        ep_cur = __expf(PRnxt_);                                              \
        mk_cur = m_sh[(t_) + 1];                                              \
    } while (0)

    // main loop: groups of 4 (t = tb..tb+3), renorm at the t%4==0 slot
    for (int tb = 1; tb + 3 < T_; tb += 4) {
        STEP(tb + 0, pr0, pr1, false, 0, 1);
        STEP(tb + 1, pr1, pr2, false, 1, 0);
        STEP(tb + 2, pr2, pr3, false, 0, 1);
        STEP(tb + 3, pr3, pr0, true,  1, 0);
    }
    // epilogue: t = 1021, 1022, 1023
    STEP(T_ - 3, pr0, pr1, false, 0, 1);
    STEP(T_ - 2, pr1, pr2, false, 1, 0);
    STEP(T_ - 1, pr2, pr3, false, 0, 1);

#undef STEP
#undef PLOAD

    __syncthreads();   // realign warps (barrier 0, independent of ids 1..8)

    // den[b] = logZ + log( sum_j u[j] * exp(end[j]) )
    float v = u * __expf(endv[j]);
#pragma unroll
    for (int off = 16; off; off >>= 1)
        v += __shfl_xor_sync(0xffffffffu, v, off);
    if (lane == 0) red[w] = v;
    __syncthreads();
    if (j == 0) {
        float s = (red[0] + red[1]) + (red[2] + red[3]);
        g_den[b] = logZ + __logf(s);
    }
}

// ---------------------------------------------------------------------------
// Numerator: path score. One block per batch b, 256 threads stride over t.
// Targets may be int64 or int32 (JAX x64 off) — sniff at runtime.
// ---------------------------------------------------------------------------
__global__ __launch_bounds__(256) void crf_num_kernel(
    const float* __restrict__ pred,
    const void*  __restrict__ tgt_raw,
    const int*   __restrict__ mask,
    const float* __restrict__ trans,
    const float* __restrict__ start,
    const float* __restrict__ endv)
{
    const int b    = blockIdx.x;
    const int tid  = threadIdx.x;
    const int lane = tid & 31;
    const int wid  = tid >> 5;

    __shared__ int s_is64;
    if (tid == 0) {
        const unsigned int* wp = (const unsigned int*)tgt_raw;
        int is64 = 1;
#pragma unroll
        for (int k = 0; k < 32; ++k)
            if (wp[2 * k + 1] != 0u) { is64 = 0; break; }
        s_is64 = is64;
    }
    __syncthreads();
    const int is64 = s_is64;
    const long long* t64 = (const long long*)tgt_raw;
    const int*       t32 = (const int*)tgt_raw;

    float local = 0.0f;
    int   mcnt  = 0;

    for (int t = tid; t < T_; t += 256) {
        const int mk = mask[t * B_ + b];
        mcnt += mk;
        if (t >= 1 && mk) {
            const int cur = is64 ? (int)t64[t * B_ + b]       : t32[t * B_ + b];
            const int prv = is64 ? (int)t64[(t - 1) * B_ + b] : t32[(t - 1) * B_ + b];
            local += trans[prv * L_ + cur] +
                     pred[(size_t)t * STRIDE_ + b * L_ + cur];
        }
    }

    __shared__ float sf[8];
    __shared__ int   si[8];
#pragma unroll
    for (int off = 16; off; off >>= 1) {
        local += __shfl_xor_sync(0xffffffffu, local, off);
        mcnt  += __shfl_xor_sync(0xffffffffu, mcnt,  off);
    }
    if (lane == 0) { sf[wid] = local; si[wid] = mcnt; }
    __syncthreads();

    if (tid == 0) {
        float tot = 0.0f;
        int   mt  = 0;
#pragma unroll
        for (int q = 0; q < 8; ++q) { tot += sf[q]; mt += si[q]; }
        const int t0 = is64 ? (int)t64[b] : t32[b];
        float sc = start[t0] + pred[b * L_ + t0] + tot;
        const int last = mt - 1;
        const int tl = is64 ? (int)t64[last * B_ + b] : t32[last * B_ + b];
        sc += endv[tl];
        g_num[b] = sc;
    }
}

// ---------------------------------------------------------------------------
// Final: out = mean(den - num)
// ---------------------------------------------------------------------------
__global__ __launch_bounds__(B_) void crf_final_kernel(float* __restrict__ out)
{
    const int j    = threadIdx.x;
    const int lane = j & 31;
    const int wid  = j >> 5;

    float v = g_den[j] - g_num[j];
    __shared__ float red[4];
#pragma unroll
    for (int off = 16; off; off >>= 1)
        v += __shfl_xor_sync(0xffffffffu, v, off);
    if (lane == 0) red[wid] = v;
    __syncthreads();
    if (j == 0)
        out[0] = ((red[0] + red[1]) + (red[2] + red[3])) * (1.0f / (float)B_);
}

extern "C" void kernel_launch(void* const* d_in, const int* in_sizes, int n_in,
                              void* d_out, int out_size)
{
    const float* pred  = (const float*)d_in[0];
    const void*  tgt   = (const void*)d_in[1];
    const int*   mask  = (const int*)d_in[2];
    const float* trans = (const float*)d_in[3];
    const float* start = (const float*)d_in[4];
    const float* endv  = (const float*)d_in[5];
    float* out = (float*)d_out;

    crf_den_kernel<<<B_, L_>>>(pred, mask, trans, start, endv);
    crf_num_kernel<<<B_, 256>>>(pred, tgt, mask, trans, start, endv);
    crf_final_kernel<<<1, B_>>>(out);
}

// round 10
// speedup vs baseline: 2.4189x; 2.4189x over previous
#include <cuda_runtime.h>

#define T_ 1024
#define B_ 128
#define L_ 128
#define STRIDE_ (B_ * L_)

typedef unsigned long long ull;

// scratch (no allocations allowed)
__device__ float g_den[B_];
__device__ float g_num[B_];

__device__ __forceinline__ ull ffma2(ull a, ull b, ull c) {
    ull d;
    asm("fma.rn.f32x2 %0, %1, %2, %3;" : "=l"(d) : "l"(a), "l"(b), "l"(c));
    return d;
}
__device__ __forceinline__ ull add2(ull a, ull b) {
    ull d;
    asm("add.rn.f32x2 %0, %1, %2;" : "=l"(d) : "l"(a), "l"(b));
    return d;
}
__device__ __forceinline__ ull pack2(float lo, float hi) {
    ull d;
    asm("mov.b64 %0, {%1, %2};" : "=l"(d) : "f"(lo), "f"(hi));
    return d;
}
__device__ __forceinline__ float2 unpack2(ull v) {
    float2 f;
    asm("mov.b64 {%0, %1}, %2;" : "=f"(f.x), "=f"(f.y) : "l"(v));
    return f;
}

#define CBAR(id) asm volatile("bar.sync %0, 128;" :: "r"(id) : "memory")

// The full forward pass is linear: den = log(e_endT · M_1023···M_1 · u_0),
// with (M_t x)[j] = exp(p_t[j]) * sum_i expT[i][j] x[i]  (identity if mask=0).
// Split the product: forward half u_A = M_511···M_1 u_0 (511 steps) and
// backward half v_B = M_512^T···M_1023^T e_end (512 steps). Then
//   den = logZ_A + logZ_B + log(u_A · v_B).
// The two halves are INDEPENDENT chains -> run both in one 256-thread CTA
// (one warp of each per SMSP; they hide each other's latency — measured
// 1.81x per-SM throughput in the dual-chain experiment). Grid = 128 CTAs.
// Transposed apply: (M^T v)[i] = sum_j expT[i][j] * (ep[j] v[j]) —
// elementwise multiply BEFORE the exchange, rows of expT instead of columns.
// Both halves renormalize by the broadcast element 0 of the exchanged vector
// every 4 steps (exact for any consistent positive scale; proven rel_err 0).

// dot of exchanged vector (smem, pairs) against rT2 (64 packed regs)
#define DOT128(EVBASE_, PART_)                                                \
    do {                                                                      \
        const ulonglong2* ev = reinterpret_cast<const ulonglong2*>(EVBASE_);  \
        ull c0 = 0ull, c1 = 0ull, c2 = 0ull, c3 = 0ull;                       \
        ull c4 = 0ull, c5 = 0ull, c6 = 0ull, c7 = 0ull;                       \
        _Pragma("unroll")                                                     \
        for (int i = 0; i < 8; ++i) {                                         \
            ulonglong2 x = ev[4 * i];                                         \
            ulonglong2 y = ev[4 * i + 1];                                     \
            ulonglong2 z = ev[4 * i + 2];                                     \
            ulonglong2 q = ev[4 * i + 3];                                     \
            c0 = ffma2(x.x, rT2[8 * i + 0], c0);                              \
            c1 = ffma2(x.y, rT2[8 * i + 1], c1);                              \
            c2 = ffma2(y.x, rT2[8 * i + 2], c2);                              \
            c3 = ffma2(y.y, rT2[8 * i + 3], c3);                              \
            c4 = ffma2(z.x, rT2[8 * i + 4], c4);                              \
            c5 = ffma2(z.y, rT2[8 * i + 5], c5);                              \
            c6 = ffma2(q.x, rT2[8 * i + 6], c6);                              \
            c7 = ffma2(q.y, rT2[8 * i + 7], c7);                              \
        }                                                                     \
        c0 = add2(c0, c1); c2 = add2(c2, c3);                                 \
        c4 = add2(c4, c5); c6 = add2(c6, c7);                                 \
        c0 = add2(c0, c2); c4 = add2(c4, c6);                                 \
        c0 = add2(c0, c4);                                                    \
        float2 fx = unpack2(c0);                                              \
        PART_ = fx.x + fx.y;                                                  \
    } while (0)

__global__ __launch_bounds__(256, 1) void crf_den_kernel(
    const float* __restrict__ pred,    // (T,B,L)
    const int*   __restrict__ mask,    // (T,B)
    const float* __restrict__ trans,   // (L,L)
    const float* __restrict__ start,   // (L)
    const float* __restrict__ endv)    // (L)
{
    const int tid   = threadIdx.x;
    const int chain = tid >> 7;          // 0 = forward half, 1 = backward half
    const int j     = tid & 127;
    const int lane  = tid & 31;
    const int wloc  = (tid >> 5) & 3;
    const int b     = blockIdx.x;

    __shared__ __align__(16) float eA[2][L_];   // forward exchange
    __shared__ __align__(16) float eB[2][L_];   // backward exchange
    __shared__ int   m_sh[T_];
    __shared__ float red[4];
    __shared__ float zsh[2];

    // mask column b, loaded cooperatively by all 256 threads
    for (int t = tid; t < T_; t += 256)
        m_sh[t] = mask[t * B_ + b];

    const float* pj = pred + b * L_ + j;

    // exp(transitions): fwd thread j needs COLUMN j (pairs over i);
    // bwd thread j needs ROW j (pairs over the summed index jj).
    ull rT2[64];
    if (chain == 0) {
#pragma unroll
        for (int k = 0; k < 64; ++k)
            rT2[k] = pack2(expf(trans[(2 * k) * L_ + j]),
                           expf(trans[(2 * k + 1) * L_ + j]));
    } else {
#pragma unroll
        for (int k = 0; k < 64; ++k)
            rT2[k] = pack2(expf(trans[j * L_ + 2 * k]),
                           expf(trans[j * L_ + 2 * k + 1]));
    }

    float u;              // chain 0: u ; chain 1: v
    float logZ = 0.0f;
    int   buf  = 0;

    if (chain == 0) {
        u = __expf(start[j] + pj[0]);   // u_0
        eA[0][j] = u;
    } else {
        u = __expf(endv[j]);            // v_T
    }
    __syncthreads();   // init stores + m_sh visible to everyone

    if (chain == 0) {
        // ---------------- forward half: t = 1 .. 511 ----------------
        float pr0 = pj[(size_t)1 << 14];
        float pr1 = pj[(size_t)2 << 14];
        float pr2 = pj[(size_t)3 << 14];
        float pr3 = pj[(size_t)4 << 14];
        float ep_cur = __expf(pr0);
        int   mk_cur = m_sh[1];

#define FSTEP(t_, PRc_, PRn_, RN_)                                            \
    do {                                                                      \
        float part;                                                          \
        DOT128(&eA[buf][0], part);                                            \
        float inv_m = 1.0f;                                                   \
        if (RN_) {                                                            \
            const float mv = eA[buf][0];                                      \
            logZ += __logf(mv);                                               \
            inv_m = 1.0f / mv;                                                \
        }                                                                     \
        u = (mk_cur ? part * ep_cur : u) * inv_m;                             \
        buf ^= 1;                                                             \
        eA[buf][j] = u;                                                       \
        CBAR(1);                                                              \
        PRc_ = pj[(size_t)((t_) + 4) << 14];  /* t+4 <= 515, in-bounds */     \
        ep_cur = __expf(PRn_);                                                \
        mk_cur = m_sh[(t_) + 1];                                              \
    } while (0)

        for (int tb = 1; tb + 3 <= 508; tb += 4) {   // t = 1 .. 508
            FSTEP(tb + 0, pr0, pr1, false);
            FSTEP(tb + 1, pr1, pr2, false);
            FSTEP(tb + 2, pr2, pr3, false);
            FSTEP(tb + 3, pr3, pr0, true);
        }
        FSTEP(509, pr0, pr1, false);
        FSTEP(510, pr1, pr2, false);
        FSTEP(511, pr2, pr3, false);
#undef FSTEP
    } else {
        // ---------------- backward half: t = 1023 .. 512 ----------------
        float pr0 = pj[(size_t)1023 << 14];
        float pr1 = pj[(size_t)1022 << 14];
        float pr2 = pj[(size_t)1021 << 14];
        float pr3 = pj[(size_t)1020 << 14];
        float ep_cur = __expf(pr0);
        int   mk_cur = m_sh[1023];

#define BSTEP(t_, PRc_, PRn_, RN_)                                            \
    do {                                                                      \
        eB[buf][j] = ep_cur * u;        /* w = ep_t ⊙ v */                    \
        CBAR(2);                                                              \
        float part;                                                          \
        DOT128(&eB[buf][0], part);                                            \
        float inv_m = 1.0f;                                                   \
        if (RN_) {                                                            \
            const float mv = eB[buf][0];                                      \
            logZ += __logf(mv);                                               \
            inv_m = 1.0f / mv;                                                \
        }                                                                     \
        u = (mk_cur ? part : u) * inv_m;                                      \
        buf ^= 1;                                                             \
        PRc_ = pj[(size_t)((t_) - 4) << 14];  /* t-4 >= 508, in-bounds */     \
        ep_cur = __expf(PRn_);                                                \
        mk_cur = m_sh[(t_) - 1];                                              \
    } while (0)

        for (int tb = 1023; tb - 3 >= 512; tb -= 4) {   // t = 1023 .. 512
            BSTEP(tb - 0, pr0, pr1, false);
            BSTEP(tb - 1, pr1, pr2, false);
            BSTEP(tb - 2, pr2, pr3, false);
            BSTEP(tb - 3, pr3, pr0, true);
        }
#undef BSTEP
    }

    __syncthreads();   // both halves done

    // publish final vectors and partial logZs
    if (chain == 0) eA[0][j] = u;
    else            eB[0][j] = u;
    if (j == 0) zsh[chain] = logZ;
    __syncthreads();

    // den[b] = logZ_A + logZ_B + log( sum_j u_A[j] * v_B[j] )
    if (chain == 0) {
        float v = eA[0][j] * eB[0][j];
#pragma unroll
        for (int off = 16; off; off >>= 1)
            v += __shfl_xor_sync(0xffffffffu, v, off);
        if (lane == 0) red[wloc] = v;
    }
    __syncthreads();
    if (tid == 0) {
        float s = (red[0] + red[1]) + (red[2] + red[3]);
        g_den[b] = zsh[0] + zsh[1] + __logf(s);
    }
}

// ---------------------------------------------------------------------------
// Numerator: path score. One block per batch b, 256 threads stride over t.
// Targets may be int64 or int32 (JAX x64 off) — sniff at runtime.
// ---------------------------------------------------------------------------
__global__ __launch_bounds__(256) void crf_num_kernel(
    const float* __restrict__ pred,
    const void*  __restrict__ tgt_raw,
    const int*   __restrict__ mask,
    const float* __restrict__ trans,
    const float* __restrict__ start,
    const float* __restrict__ endv)
{
    const int b    = blockIdx.x;
    const int tid  = threadIdx.x;
    const int lane = tid & 31;
    const int wid  = tid >> 5;

    __shared__ int s_is64;
    if (tid == 0) {
        const unsigned int* wp = (const unsigned int*)tgt_raw;
        int is64 = 1;
#pragma unroll
        for (int k = 0; k < 32; ++k)
            if (wp[2 * k + 1] != 0u) { is64 = 0; break; }
        s_is64 = is64;
    }
    __syncthreads();
    const int is64 = s_is64;
    const long long* t64 = (const long long*)tgt_raw;
    const int*       t32 = (const int*)tgt_raw;

    float local = 0.0f;
    int   mcnt  = 0;

    for (int t = tid; t < T_; t += 256) {
        const int mk = mask[t * B_ + b];
        mcnt += mk;
        if (t >= 1 && mk) {
            const int cur = is64 ? (int)t64[t * B_ + b]       : t32[t * B_ + b];
            const int prv = is64 ? (int)t64[(t - 1) * B_ + b] : t32[(t - 1) * B_ + b];
            local += trans[prv * L_ + cur] +
                     pred[(size_t)t * STRIDE_ + b * L_ + cur];
        }
    }

    __shared__ float sf[8];
    __shared__ int   si[8];
#pragma unroll
    for (int off = 16; off; off >>= 1) {
        local += __shfl_xor_sync(0xffffffffu, local, off);
        mcnt  += __shfl_xor_sync(0xffffffffu, mcnt,  off);
    }
    if (lane == 0) { sf[wid] = local; si[wid] = mcnt; }
    __syncthreads();

    if (tid == 0) {
        float tot = 0.0f;
        int   mt  = 0;
#pragma unroll
        for (int q = 0; q < 8; ++q) { tot += sf[q]; mt += si[q]; }
        const int t0 = is64 ? (int)t64[b] : t32[b];
        float sc = start[t0] + pred[b * L_ + t0] + tot;
        const int last = mt - 1;
        const int tl = is64 ? (int)t64[last * B_ + b] : t32[last * B_ + b];
        sc += endv[tl];
        g_num[b] = sc;
    }
}

// ---------------------------------------------------------------------------
// Final: out = mean(den - num)
// ---------------------------------------------------------------------------
__global__ __launch_bounds__(B_) void crf_final_kernel(float* __restrict__ out)
{
    const int j    = threadIdx.x;
    const int lane = j & 31;
    const int wid  = j >> 5;

    float v = g_den[j] - g_num[j];
    __shared__ float red[4];
#pragma unroll
    for (int off = 16; off; off >>= 1)
        v += __shfl_xor_sync(0xffffffffu, v, off);
    if (lane == 0) red[wid] = v;
    __syncthreads();
    if (j == 0)
        out[0] = ((red[0] + red[1]) + (red[2] + red[3])) * (1.0f / (float)B_);
}

extern "C" void kernel_launch(void* const* d_in, const int* in_sizes, int n_in,
                              void* d_out, int out_size)
{
    const float* pred  = (const float*)d_in[0];
    const void*  tgt   = (const void*)d_in[1];
    const int*   mask  = (const int*)d_in[2];
    const float* trans = (const float*)d_in[3];
    const float* start = (const float*)d_in[4];
    const float* endv  = (const float*)d_in[5];
    float* out = (float*)d_out;

    crf_den_kernel<<<B_, 256>>>(pred, mask, trans, start, endv);
    crf_num_kernel<<<B_, 256>>>(pred, tgt, mask, trans, start, endv);
    crf_final_kernel<<<1, B_>>>(out);
}